// round 1
// baseline (speedup 1.0000x reference)
#include <cuda_runtime.h>
#include <math.h>

#define HIDDEN 128
#define MAXN 50000
#define MAXE 800000

// ---------------- scratch (device globals: no allocation allowed) ----------
__device__ float g_h[(size_t)MAXN * HIDDEN];    // h = x @ W^T + b
__device__ float g_agg[(size_t)MAXN * HIDDEN];  // segment-summed messages
__device__ float g_deg[MAXN];                   // in-degree (float; exact for counts)
__device__ float g_norm[MAXE];                  // per-edge norm

// ---------------- degree ----------------------------------------------------
__global__ void deg_kernel(const int* __restrict__ dst, int e) {
    int i = blockIdx.x * blockDim.x + threadIdx.x;
    if (i < e) atomicAdd(&g_deg[dst[i]], 1.0f);
}

// ---------------- per-edge norm ---------------------------------------------
__global__ void norm_kernel(const int* __restrict__ src, const int* __restrict__ dst, int e) {
    int i = blockIdx.x * blockDim.x + threadIdx.x;
    if (i < e) {
        float ds = g_deg[src[i]];
        float dd = g_deg[dst[i]];
        g_norm[i] = rsqrtf(ds) * rsqrtf(dd);
    }
}

// ---------------- GEMM: C[n,128] = A[n,128] @ W^T + b, optional exact GELU --
// Block: 256 threads (tx=tid&31 over 32 col-groups of 4, ty=tid>>5 over 8 row-
// groups of 8). Tile: 64 rows x 128 cols, full K=128 resident in smem.
// W is transposed into smem (stride 132 words -> 16B-aligned rows, spread banks).
#define GEMM_ROWS 64
#define WT_STRIDE 132

template <bool GELU>
__global__ void __launch_bounds__(256, 2)
gemm_bias_kernel(const float* __restrict__ A, const float* __restrict__ W,
                 const float* __restrict__ b, float* __restrict__ C, int n) {
    extern __shared__ float smem[];
    float* As = smem;                       // 64*128 floats = 32 KB
    float* Wt = smem + GEMM_ROWS * HIDDEN;  // 128*132 floats = 67.6 KB

    const int tid  = threadIdx.x;
    const int row0 = blockIdx.x * GEMM_ROWS;

    // Load W transposed: W[j][k] -> Wt[k*132 + j]. Global read coalesced over k.
    for (int i = tid; i < HIDDEN * HIDDEN; i += 256) {
        int j = i >> 7;
        int k = i & 127;
        Wt[k * WT_STRIDE + j] = W[i];
    }

    // Load A tile (float4, coalesced); OOB rows -> zeros.
    const float4* A4 = reinterpret_cast<const float4*>(A);
    for (int i = tid; i < GEMM_ROWS * 32; i += 256) {
        int r  = i >> 5;
        int c4 = i & 31;
        int gr = row0 + r;
        float4 v = (gr < n) ? A4[(size_t)gr * 32 + c4] : make_float4(0.f, 0.f, 0.f, 0.f);
        *reinterpret_cast<float4*>(&As[r * HIDDEN + c4 * 4]) = v;
    }
    __syncthreads();

    const int tx = tid & 31;   // col group: cols tx*4 .. tx*4+3
    const int ty = tid >> 5;   // row group: rows ty*8 .. ty*8+7

    float acc[8][4];
#pragma unroll
    for (int i = 0; i < 8; i++)
#pragma unroll
        for (int q = 0; q < 4; q++) acc[i][q] = 0.f;

    const float* as_base = &As[ty * 8 * HIDDEN];

#pragma unroll 4
    for (int k0 = 0; k0 < HIDDEN; k0 += 4) {
        // 4 consecutive k-rows of W^T, 4 columns each (float4)
        float4 w0 = *reinterpret_cast<const float4*>(&Wt[(k0 + 0) * WT_STRIDE + tx * 4]);
        float4 w1 = *reinterpret_cast<const float4*>(&Wt[(k0 + 1) * WT_STRIDE + tx * 4]);
        float4 w2 = *reinterpret_cast<const float4*>(&Wt[(k0 + 2) * WT_STRIDE + tx * 4]);
        float4 w3 = *reinterpret_cast<const float4*>(&Wt[(k0 + 3) * WT_STRIDE + tx * 4]);
#pragma unroll
        for (int i = 0; i < 8; i++) {
            float4 a = *reinterpret_cast<const float4*>(&as_base[i * HIDDEN + k0]);
            acc[i][0] += a.x * w0.x; acc[i][1] += a.x * w0.y; acc[i][2] += a.x * w0.z; acc[i][3] += a.x * w0.w;
            acc[i][0] += a.y * w1.x; acc[i][1] += a.y * w1.y; acc[i][2] += a.y * w1.z; acc[i][3] += a.y * w1.w;
            acc[i][0] += a.z * w2.x; acc[i][1] += a.z * w2.y; acc[i][2] += a.z * w2.z; acc[i][3] += a.z * w2.w;
            acc[i][0] += a.w * w3.x; acc[i][1] += a.w * w3.y; acc[i][2] += a.w * w3.z; acc[i][3] += a.w * w3.w;
        }
    }

    // bias (+ optional exact-erf GELU), store
    float4 bv = reinterpret_cast<const float4*>(b)[tx];
#pragma unroll
    for (int i = 0; i < 8; i++) {
        int gr = row0 + ty * 8 + i;
        if (gr < n) {
            float4 o;
            o.x = acc[i][0] + bv.x;
            o.y = acc[i][1] + bv.y;
            o.z = acc[i][2] + bv.z;
            o.w = acc[i][3] + bv.w;
            if (GELU) {
                o.x = 0.5f * o.x * (1.0f + erff(o.x * 0.70710678118654752f));
                o.y = 0.5f * o.y * (1.0f + erff(o.y * 0.70710678118654752f));
                o.z = 0.5f * o.z * (1.0f + erff(o.z * 0.70710678118654752f));
                o.w = 0.5f * o.w * (1.0f + erff(o.w * 0.70710678118654752f));
            }
            *reinterpret_cast<float4*>(&C[(size_t)gr * HIDDEN + tx * 4]) = o;
        }
    }
}

// ---------------- scatter: agg[dst] += h[src] * norm ------------------------
// One warp per edge; lane = 4-float chunk. Gather and red are both 512B
// fully-coalesced per warp. h (25.6MB) and agg (25.6MB) are L2-resident.
__global__ void __launch_bounds__(256)
scatter_kernel(const int* __restrict__ src, const int* __restrict__ dst, int e) {
    unsigned gid  = blockIdx.x * 256u + threadIdx.x;
    unsigned edge = gid >> 5;
    unsigned c    = (gid & 31u) * 4u;
    if (edge >= (unsigned)e) return;

    int s   = __ldg(&src[edge]);
    int d   = __ldg(&dst[edge]);
    float w = __ldg(&g_norm[edge]);

    float4 v = *reinterpret_cast<const float4*>(&g_h[(size_t)s * HIDDEN + c]);
    v.x *= w; v.y *= w; v.z *= w; v.w *= w;

    float* p = &g_agg[(size_t)d * HIDDEN + c];
    asm volatile("red.global.add.v4.f32 [%0], {%1, %2, %3, %4};"
                 :: "l"(p), "f"(v.x), "f"(v.y), "f"(v.z), "f"(v.w)
                 : "memory");
}

// ---------------- launch -----------------------------------------------------
extern "C" void kernel_launch(void* const* d_in, const int* in_sizes, int n_in,
                              void* d_out, int out_size) {
    const float* x  = (const float*)d_in[0];
    const float* W  = (const float*)d_in[1];
    const float* b  = (const float*)d_in[2];
    const int* ei   = (const int*)d_in[3];

    const int n = in_sizes[0] / HIDDEN;   // 50000
    const int e = in_sizes[3] / 2;        // 800000
    const int* src = ei;
    const int* dst = ei + e;

    float* out = (float*)d_out;

    // scratch addresses for async memset (no allocation; symbols are static)
    static float* p_agg = nullptr;
    static float* p_deg = nullptr;
    if (!p_agg) {
        cudaGetSymbolAddress((void**)&p_agg, g_agg);
        cudaGetSymbolAddress((void**)&p_deg, g_deg);
    }

    const size_t smem_bytes = (GEMM_ROWS * HIDDEN + HIDDEN * WT_STRIDE) * sizeof(float);
    cudaFuncSetAttribute(gemm_bias_kernel<false>,
                         cudaFuncAttributeMaxDynamicSharedMemorySize, (int)smem_bytes);
    cudaFuncSetAttribute(gemm_bias_kernel<true>,
                         cudaFuncAttributeMaxDynamicSharedMemorySize, (int)smem_bytes);

    // 1) zero deg + agg (capturable memset nodes)
    cudaMemsetAsync(p_deg, 0, (size_t)n * sizeof(float));
    cudaMemsetAsync(p_agg, 0, (size_t)n * HIDDEN * sizeof(float));

    // 2) degree
    deg_kernel<<<(e + 255) / 256, 256>>>(dst, e);

    // 3) per-edge norm
    norm_kernel<<<(e + 255) / 256, 256>>>(src, dst, e);

    // 4) h = x @ W^T + b
    float* h;
    cudaGetSymbolAddress((void**)&h, g_h);
    int gemm_blocks = (n + GEMM_ROWS - 1) / GEMM_ROWS;
    gemm_bias_kernel<false><<<gemm_blocks, 256, smem_bytes>>>(x, W, b, h, n);

    // 5) scatter: agg[dst] += h[src] * norm
    unsigned long long work = (unsigned long long)e * 32ull;
    unsigned sblocks = (unsigned)((work + 255ull) / 256ull);
    scatter_kernel<<<sblocks, 256>>>(src, dst, e);

    // 6) out = gelu(agg @ W^T + b)
    float* agg;
    cudaGetSymbolAddress((void**)&agg, g_agg);
    gemm_bias_kernel<true><<<gemm_blocks, 256, smem_bytes>>>(agg, W, b, out, n);
}

// round 2
// speedup vs baseline: 1.2822x; 1.2822x over previous
#include <cuda_runtime.h>
#include <math.h>

#define HIDDEN 128
#define MAXN 50000
#define MAXE 800000

// ---------------- scratch (device globals: no allocation allowed) ----------
__device__ float g_h[(size_t)MAXN * HIDDEN];    // h = x @ W^T + b
__device__ float g_agg[(size_t)MAXN * HIDDEN];  // gathered messages
__device__ int   g_degi[MAXN];                  // in-degree (int)
__device__ float g_dinv[MAXN];                  // deg^-1/2
__device__ int   g_off[MAXN + 1];               // CSR row offsets (by dst)
__device__ int   g_cur[MAXN];                   // fill cursors
__device__ int2  g_edge[MAXE];                  // packed (src, norm-bits) per CSR slot
__device__ int   g_bsum[64];                    // block sums for scan

// ---------------- degree (int) ----------------------------------------------
__global__ void deg_kernel(const int* __restrict__ dst, int e) {
    int i = blockIdx.x * blockDim.x + threadIdx.x;
    if (i < e) atomicAdd(&g_degi[dst[i]], 1);
}

// ---------------- deg^-1/2 ---------------------------------------------------
__global__ void dinv_kernel(int n) {
    int i = blockIdx.x * blockDim.x + threadIdx.x;
    if (i < n) g_dinv[i] = rsqrtf((float)g_degi[i]);
}

// ---------------- 3-kernel exclusive scan of degrees -> g_off ---------------
__global__ void scan_block_kernel(int n) {
    __shared__ int sh[1024];
    int t = threadIdx.x;
    int i = blockIdx.x * 1024 + t;
    int v = (i < n) ? g_degi[i] : 0;
    sh[t] = v;
    __syncthreads();
    for (int d = 1; d < 1024; d <<= 1) {
        int x = (t >= d) ? sh[t - d] : 0;
        __syncthreads();
        sh[t] += x;
        __syncthreads();
    }
    if (i < n) g_off[i + 1] = sh[t];           // inclusive within block
    if (t == 1023) g_bsum[blockIdx.x] = sh[1023];
    if (i == 0) g_off[0] = 0;
}

__global__ void scan_sums_kernel(int nb) {
    __shared__ int sh[64];
    int t = threadIdx.x;
    sh[t] = (t < nb) ? g_bsum[t] : 0;
    __syncthreads();
    for (int d = 1; d < 64; d <<= 1) {
        int x = (t >= d) ? sh[t - d] : 0;
        __syncthreads();
        sh[t] += x;
        __syncthreads();
    }
    if (t < nb) g_bsum[t] = sh[t];             // inclusive block prefix
}

__global__ void scan_add_kernel(int n) {
    int i = blockIdx.x * blockDim.x + threadIdx.x;
    if (i < n) {
        int blk = i >> 10;
        if (blk > 0) g_off[i + 1] += g_bsum[blk - 1];
    }
}

// ---------------- CSR fill: slot per edge, packed (src, norm) ---------------
__global__ void fill_kernel(const int* __restrict__ src, const int* __restrict__ dst, int e) {
    int i = blockIdx.x * blockDim.x + threadIdx.x;
    if (i < e) {
        int s = src[i];
        int d = dst[i];
        int pos = g_off[d] + atomicAdd(&g_cur[d], 1);
        int2 ew;
        ew.x = s;
        ew.y = __float_as_int(g_dinv[s] * g_dinv[d]);
        g_edge[pos] = ew;
    }
}

// ---------------- gather: agg[i] = sum_e norm * h[src] ----------------------
// One warp per dst node; lane owns a float4 column chunk. No atomics, agg
// written exactly once (no memset needed).
__global__ void __launch_bounds__(256)
gather_kernel(int n) {
    int warp = (blockIdx.x * 256 + threadIdx.x) >> 5;
    int lane = threadIdx.x & 31;
    if (warp >= n) return;
    int p  = g_off[warp];
    int pe = g_off[warp + 1];
    const float4* h4 = reinterpret_cast<const float4*>(g_h);
    float4 acc = make_float4(0.f, 0.f, 0.f, 0.f);
    // two edges per iteration for load-level parallelism
    for (; p + 1 < pe; p += 2) {
        int2 e0 = __ldg(&g_edge[p]);
        int2 e1 = __ldg(&g_edge[p + 1]);
        float4 v0 = h4[(size_t)e0.x * 32 + lane];
        float4 v1 = h4[(size_t)e1.x * 32 + lane];
        float w0 = __int_as_float(e0.y);
        float w1 = __int_as_float(e1.y);
        acc.x += w0 * v0.x + w1 * v1.x;
        acc.y += w0 * v0.y + w1 * v1.y;
        acc.z += w0 * v0.z + w1 * v1.z;
        acc.w += w0 * v0.w + w1 * v1.w;
    }
    if (p < pe) {
        int2 e0 = __ldg(&g_edge[p]);
        float4 v0 = h4[(size_t)e0.x * 32 + lane];
        float w0 = __int_as_float(e0.y);
        acc.x += w0 * v0.x; acc.y += w0 * v0.y;
        acc.z += w0 * v0.z; acc.w += w0 * v0.w;
    }
    reinterpret_cast<float4*>(g_agg)[(size_t)warp * 32 + lane] = acc;
}

// ---------------- packed f32x2 helpers ---------------------------------------
__device__ __forceinline__ unsigned long long f32x2_pack(float lo, float hi) {
    unsigned long long r;
    asm("mov.b64 %0, {%1, %2};" : "=l"(r) : "f"(lo), "f"(hi));
    return r;
}
__device__ __forceinline__ void f32x2_fma(unsigned long long& d,
                                          unsigned long long a, unsigned long long b) {
    asm("fma.rn.f32x2 %0, %1, %2, %0;" : "+l"(d) : "l"(a), "l"(b));
}
__device__ __forceinline__ float2 f32x2_unpack(unsigned long long v) {
    float2 r;
    asm("mov.b64 {%0, %1}, %2;" : "=f"(r.x), "=f"(r.y) : "l"(v));
    return r;
}

__device__ __forceinline__ float gelu_exact(float v) {
    return 0.5f * v * (1.0f + erff(v * 0.70710678118654752f));
}

// ---------------- GEMM: C[n,128] = A[n,128] @ W^T + b (opt. exact GELU) -----
// FFMA2 version: A tile stored k-major (row pairs load as packed b64,
// broadcast across warp); W col-padded. Thread tile 8 rows (4 packed pairs)
// x 4 cols. 16 FFMA2 + 4 packs + 4 LDS.64 + 1 LDS.128 per k.
#define GEMM_ROWS 64
#define WT_STRIDE 132
#define AT_STRIDE 66

template <bool GELU>
__global__ void __launch_bounds__(256, 2)
gemm_bias_kernel(const float* __restrict__ A, const float* __restrict__ W,
                 const float* __restrict__ b, float* __restrict__ C, int n) {
    extern __shared__ float smem[];
    float* Wt = smem;                          // [k][j], stride 132: 67.6 KB
    float* At = smem + HIDDEN * WT_STRIDE;     // [k][r], stride 66:  33.8 KB

    const int tid  = threadIdx.x;
    const int row0 = blockIdx.x * GEMM_ROWS;

    // W[j][k] -> Wt[k*132 + j] (coalesced global reads along k)
    for (int i = tid; i < HIDDEN * HIDDEN; i += 256) {
        int j = i >> 7;
        int k = i & 127;
        Wt[k * WT_STRIDE + j] = W[i];
    }
    // A tile -> k-major At[k*66 + r]
    const float4* A4 = reinterpret_cast<const float4*>(A);
    for (int i = tid; i < GEMM_ROWS * 32; i += 256) {
        int r  = i >> 5;
        int c4 = i & 31;
        int gr = row0 + r;
        float4 v = (gr < n) ? A4[(size_t)gr * 32 + c4] : make_float4(0.f, 0.f, 0.f, 0.f);
        At[(4 * c4 + 0) * AT_STRIDE + r] = v.x;
        At[(4 * c4 + 1) * AT_STRIDE + r] = v.y;
        At[(4 * c4 + 2) * AT_STRIDE + r] = v.z;
        At[(4 * c4 + 3) * AT_STRIDE + r] = v.w;
    }
    __syncthreads();

    const int tx = tid & 31;   // col group: cols tx*4 .. tx*4+3
    const int ty = tid >> 5;   // row group: rows ty*8 .. ty*8+7

    unsigned long long acc[4][4];  // [row-pair][col], each = (row 2p, row 2p+1)
#pragma unroll
    for (int p = 0; p < 4; p++)
#pragma unroll
        for (int c = 0; c < 4; c++) acc[p][c] = 0ull;

    const float* at_base = &At[ty * 8];
    const float* wt_base = &Wt[tx * 4];

#pragma unroll 4
    for (int k = 0; k < HIDDEN; k++) {
        float4 w = *reinterpret_cast<const float4*>(&wt_base[k * WT_STRIDE]);
        unsigned long long w0 = f32x2_pack(w.x, w.x);
        unsigned long long w1 = f32x2_pack(w.y, w.y);
        unsigned long long w2 = f32x2_pack(w.z, w.z);
        unsigned long long w3 = f32x2_pack(w.w, w.w);
        const float* ak = &at_base[k * AT_STRIDE];
        unsigned long long a0 = *reinterpret_cast<const unsigned long long*>(ak + 0);
        unsigned long long a1 = *reinterpret_cast<const unsigned long long*>(ak + 2);
        unsigned long long a2 = *reinterpret_cast<const unsigned long long*>(ak + 4);
        unsigned long long a3 = *reinterpret_cast<const unsigned long long*>(ak + 6);
        f32x2_fma(acc[0][0], a0, w0); f32x2_fma(acc[0][1], a0, w1);
        f32x2_fma(acc[0][2], a0, w2); f32x2_fma(acc[0][3], a0, w3);
        f32x2_fma(acc[1][0], a1, w0); f32x2_fma(acc[1][1], a1, w1);
        f32x2_fma(acc[1][2], a1, w2); f32x2_fma(acc[1][3], a1, w3);
        f32x2_fma(acc[2][0], a2, w0); f32x2_fma(acc[2][1], a2, w1);
        f32x2_fma(acc[2][2], a2, w2); f32x2_fma(acc[2][3], a2, w3);
        f32x2_fma(acc[3][0], a3, w0); f32x2_fma(acc[3][1], a3, w1);
        f32x2_fma(acc[3][2], a3, w2); f32x2_fma(acc[3][3], a3, w3);
    }

    float4 bv = reinterpret_cast<const float4*>(b)[tx];
#pragma unroll
    for (int p = 0; p < 4; p++) {
        int r0 = row0 + ty * 8 + 2 * p;
        float2 c0 = f32x2_unpack(acc[p][0]);
        float2 c1 = f32x2_unpack(acc[p][1]);
        float2 c2 = f32x2_unpack(acc[p][2]);
        float2 c3 = f32x2_unpack(acc[p][3]);
        float4 o0 = make_float4(c0.x + bv.x, c1.x + bv.y, c2.x + bv.z, c3.x + bv.w);
        float4 o1 = make_float4(c0.y + bv.x, c1.y + bv.y, c2.y + bv.z, c3.y + bv.w);
        if (GELU) {
            o0.x = gelu_exact(o0.x); o0.y = gelu_exact(o0.y);
            o0.z = gelu_exact(o0.z); o0.w = gelu_exact(o0.w);
            o1.x = gelu_exact(o1.x); o1.y = gelu_exact(o1.y);
            o1.z = gelu_exact(o1.z); o1.w = gelu_exact(o1.w);
        }
        if (r0 < n)
            *reinterpret_cast<float4*>(&C[(size_t)r0 * HIDDEN + tx * 4]) = o0;
        if (r0 + 1 < n)
            *reinterpret_cast<float4*>(&C[(size_t)(r0 + 1) * HIDDEN + tx * 4]) = o1;
    }
}

// ---------------- launch -----------------------------------------------------
extern "C" void kernel_launch(void* const* d_in, const int* in_sizes, int n_in,
                              void* d_out, int out_size) {
    const float* x = (const float*)d_in[0];
    const float* W = (const float*)d_in[1];
    const float* b = (const float*)d_in[2];
    const int* ei  = (const int*)d_in[3];

    const int n = in_sizes[0] / HIDDEN;   // 50000
    const int e = in_sizes[3] / 2;        // 800000
    const int* src = ei;
    const int* dst = ei + e;

    float* out = (float*)d_out;

    static float* p_h   = nullptr;
    static float* p_agg = nullptr;
    static int*   p_deg = nullptr;
    static int*   p_cur = nullptr;
    if (!p_h) {
        cudaGetSymbolAddress((void**)&p_h, g_h);
        cudaGetSymbolAddress((void**)&p_agg, g_agg);
        cudaGetSymbolAddress((void**)&p_deg, g_degi);
        cudaGetSymbolAddress((void**)&p_cur, g_cur);
    }

    const size_t smem_bytes = (HIDDEN * WT_STRIDE + HIDDEN * AT_STRIDE) * sizeof(float);
    cudaFuncSetAttribute(gemm_bias_kernel<false>,
                         cudaFuncAttributeMaxDynamicSharedMemorySize, (int)smem_bytes);
    cudaFuncSetAttribute(gemm_bias_kernel<true>,
                         cudaFuncAttributeMaxDynamicSharedMemorySize, (int)smem_bytes);

    // 1) zero degree + cursors
    cudaMemsetAsync(p_deg, 0, (size_t)n * sizeof(int));
    cudaMemsetAsync(p_cur, 0, (size_t)n * sizeof(int));

    // 2) degree, deg^-1/2
    deg_kernel<<<(e + 255) / 256, 256>>>(dst, e);
    dinv_kernel<<<(n + 255) / 256, 256>>>(n);

    // 3) exclusive scan -> CSR offsets
    int nscan = (n + 1023) / 1024;  // 49 <= 64
    scan_block_kernel<<<nscan, 1024>>>(n);
    scan_sums_kernel<<<1, 64>>>(nscan);
    scan_add_kernel<<<(n + 255) / 256, 256>>>(n);

    // 4) CSR fill (packed src + norm)
    fill_kernel<<<(e + 255) / 256, 256>>>(src, dst, e);

    // 5) h = x @ W^T + b
    int gemm_blocks = (n + GEMM_ROWS - 1) / GEMM_ROWS;
    gemm_bias_kernel<false><<<gemm_blocks, 256, smem_bytes>>>(x, W, b, p_h, n);

    // 6) gather: agg[i] = sum norm * h[src]
    unsigned gthreads = (unsigned)n * 32u;
    gather_kernel<<<(gthreads + 255) / 256, 256>>>(n);

    // 7) out = gelu(agg @ W^T + b)
    gemm_bias_kernel<true><<<gemm_blocks, 256, smem_bytes>>>(p_agg, W, b, out, n);
}

// round 3
// speedup vs baseline: 1.4071x; 1.0974x over previous
#include <cuda_runtime.h>
#include <math.h>

#define HIDDEN 128
#define MAXN 50000
#define MAXE 800000

// ---------------- scratch (device globals: no allocation allowed) ----------
__device__ float g_h[(size_t)MAXN * HIDDEN];    // h = x @ W^T + b
__device__ float g_agg[(size_t)MAXN * HIDDEN];  // gathered messages
__device__ int   g_degi[MAXN];                  // in-degree (int)
__device__ float g_dinv[MAXN];                  // deg^-1/2
__device__ int   g_off[MAXN + 1];               // CSR row offsets (by dst)
__device__ int   g_cur[MAXN];                   // fill cursors
__device__ int2  g_edge[MAXE];                  // packed (src, norm-bits) per CSR slot
__device__ int   g_bsum[64];                    // block sums for scan

// ---------------- degree (int) ----------------------------------------------
__global__ void deg_kernel(const int* __restrict__ dst, int e) {
    int i = blockIdx.x * blockDim.x + threadIdx.x;
    if (i < e) atomicAdd(&g_degi[dst[i]], 1);
}

// ---------------- block scan (+ fused deg^-1/2) ------------------------------
__global__ void scan_block_kernel(int n) {
    __shared__ int sh[1024];
    int t = threadIdx.x;
    int i = blockIdx.x * 1024 + t;
    int v = (i < n) ? g_degi[i] : 0;
    if (i < n) g_dinv[i] = rsqrtf((float)v);   // fused: deg^-1/2
    sh[t] = v;
    __syncthreads();
    for (int d = 1; d < 1024; d <<= 1) {
        int x = (t >= d) ? sh[t - d] : 0;
        __syncthreads();
        sh[t] += x;
        __syncthreads();
    }
    if (i < n) g_off[i + 1] = sh[t];           // inclusive within block
    if (t == 1023) g_bsum[blockIdx.x] = sh[1023];
    if (i == 0) g_off[0] = 0;
}

__global__ void scan_sums_kernel(int nb) {
    __shared__ int sh[64];
    int t = threadIdx.x;
    sh[t] = (t < nb) ? g_bsum[t] : 0;
    __syncthreads();
    for (int d = 1; d < 64; d <<= 1) {
        int x = (t >= d) ? sh[t - d] : 0;
        __syncthreads();
        sh[t] += x;
        __syncthreads();
    }
    if (t < nb) g_bsum[t] = sh[t];             // inclusive block prefix
}

__global__ void scan_add_kernel(int n) {
    int i = blockIdx.x * blockDim.x + threadIdx.x;
    if (i < n) {
        int blk = i >> 10;
        if (blk > 0) g_off[i + 1] += g_bsum[blk - 1];
    }
}

// ---------------- CSR fill: slot per edge, packed (src, norm) ---------------
__global__ void fill_kernel(const int* __restrict__ src, const int* __restrict__ dst, int e) {
    int i = blockIdx.x * blockDim.x + threadIdx.x;
    if (i < e) {
        int s = src[i];
        int d = dst[i];
        int pos = g_off[d] + atomicAdd(&g_cur[d], 1);
        int2 ew;
        ew.x = s;
        ew.y = __float_as_int(g_dinv[s] * g_dinv[d]);
        g_edge[pos] = ew;
    }
}

// ---------------- gather: agg[i] = sum_e norm * h[src] ----------------------
// One warp per dst node; lane owns a float4 column chunk. No atomics, agg
// written exactly once. 4-edge unroll for load-level parallelism.
__global__ void __launch_bounds__(256)
gather_kernel(int n) {
    int warp = (blockIdx.x * 256 + threadIdx.x) >> 5;
    int lane = threadIdx.x & 31;
    if (warp >= n) return;
    int p  = g_off[warp];
    int pe = g_off[warp + 1];
    const float4* h4 = reinterpret_cast<const float4*>(g_h);
    float4 acc = make_float4(0.f, 0.f, 0.f, 0.f);
    for (; p + 3 < pe; p += 4) {
        int2 e0 = __ldg(&g_edge[p]);
        int2 e1 = __ldg(&g_edge[p + 1]);
        int2 e2 = __ldg(&g_edge[p + 2]);
        int2 e3 = __ldg(&g_edge[p + 3]);
        float4 v0 = __ldg(&h4[(size_t)e0.x * 32 + lane]);
        float4 v1 = __ldg(&h4[(size_t)e1.x * 32 + lane]);
        float4 v2 = __ldg(&h4[(size_t)e2.x * 32 + lane]);
        float4 v3 = __ldg(&h4[(size_t)e3.x * 32 + lane]);
        float w0 = __int_as_float(e0.y);
        float w1 = __int_as_float(e1.y);
        float w2 = __int_as_float(e2.y);
        float w3 = __int_as_float(e3.y);
        acc.x += w0 * v0.x + w1 * v1.x + w2 * v2.x + w3 * v3.x;
        acc.y += w0 * v0.y + w1 * v1.y + w2 * v2.y + w3 * v3.y;
        acc.z += w0 * v0.z + w1 * v1.z + w2 * v2.z + w3 * v3.z;
        acc.w += w0 * v0.w + w1 * v1.w + w2 * v2.w + w3 * v3.w;
    }
    for (; p < pe; p++) {
        int2 e0 = __ldg(&g_edge[p]);
        float4 v0 = __ldg(&h4[(size_t)e0.x * 32 + lane]);
        float w0 = __int_as_float(e0.y);
        acc.x += w0 * v0.x; acc.y += w0 * v0.y;
        acc.z += w0 * v0.z; acc.w += w0 * v0.w;
    }
    reinterpret_cast<float4*>(g_agg)[(size_t)warp * 32 + lane] = acc;
}

// ---------------- packed f32x2 helpers ---------------------------------------
__device__ __forceinline__ unsigned long long f32x2_pack(float lo, float hi) {
    unsigned long long r;
    asm("mov.b64 %0, {%1, %2};" : "=l"(r) : "f"(lo), "f"(hi));
    return r;
}
__device__ __forceinline__ void f32x2_fma(unsigned long long& d,
                                          unsigned long long a, unsigned long long b) {
    asm("fma.rn.f32x2 %0, %1, %2, %0;" : "+l"(d) : "l"(a), "l"(b));
}
__device__ __forceinline__ float2 f32x2_unpack(unsigned long long v) {
    float2 r;
    asm("mov.b64 {%0, %1}, %2;" : "=f"(r.x), "=f"(r.y) : "l"(v));
    return r;
}

__device__ __forceinline__ float gelu_exact(float v) {
    return 0.5f * v * (1.0f + erff(v * 0.70710678118654752f));
}

// ---------------- GEMM: C[n,128] = A[n,128] @ W^T + b (opt. exact GELU) -----
// FFMA2: A tile k-major (row pairs load as packed b64), W col-padded.
// Thread tile 8 rows (4 packed pairs) x 4 cols.
#define GEMM_ROWS 64
#define WT_STRIDE 132
#define AT_STRIDE 66

template <bool GELU>
__global__ void __launch_bounds__(256, 2)
gemm_bias_kernel(const float* __restrict__ A, const float* __restrict__ W,
                 const float* __restrict__ b, float* __restrict__ C, int n) {
    extern __shared__ float smem[];
    float* Wt = smem;                          // [k][j], stride 132
    float* At = smem + HIDDEN * WT_STRIDE;     // [k][r], stride 66

    const int tid  = threadIdx.x;
    const int row0 = blockIdx.x * GEMM_ROWS;

    for (int i = tid; i < HIDDEN * HIDDEN; i += 256) {
        int j = i >> 7;
        int k = i & 127;
        Wt[k * WT_STRIDE + j] = W[i];
    }
    const float4* A4 = reinterpret_cast<const float4*>(A);
    for (int i = tid; i < GEMM_ROWS * 32; i += 256) {
        int r  = i >> 5;
        int c4 = i & 31;
        int gr = row0 + r;
        float4 v = (gr < n) ? A4[(size_t)gr * 32 + c4] : make_float4(0.f, 0.f, 0.f, 0.f);
        At[(4 * c4 + 0) * AT_STRIDE + r] = v.x;
        At[(4 * c4 + 1) * AT_STRIDE + r] = v.y;
        At[(4 * c4 + 2) * AT_STRIDE + r] = v.z;
        At[(4 * c4 + 3) * AT_STRIDE + r] = v.w;
    }
    __syncthreads();

    const int tx = tid & 31;
    const int ty = tid >> 5;

    unsigned long long acc[4][4];
#pragma unroll
    for (int p = 0; p < 4; p++)
#pragma unroll
        for (int c = 0; c < 4; c++) acc[p][c] = 0ull;

    const float* at_base = &At[ty * 8];
    const float* wt_base = &Wt[tx * 4];

#pragma unroll 4
    for (int k = 0; k < HIDDEN; k++) {
        float4 w = *reinterpret_cast<const float4*>(&wt_base[k * WT_STRIDE]);
        unsigned long long w0 = f32x2_pack(w.x, w.x);
        unsigned long long w1 = f32x2_pack(w.y, w.y);
        unsigned long long w2 = f32x2_pack(w.z, w.z);
        unsigned long long w3 = f32x2_pack(w.w, w.w);
        const float* ak = &at_base[k * AT_STRIDE];
        unsigned long long a0 = *reinterpret_cast<const unsigned long long*>(ak + 0);
        unsigned long long a1 = *reinterpret_cast<const unsigned long long*>(ak + 2);
        unsigned long long a2 = *reinterpret_cast<const unsigned long long*>(ak + 4);
        unsigned long long a3 = *reinterpret_cast<const unsigned long long*>(ak + 6);
        f32x2_fma(acc[0][0], a0, w0); f32x2_fma(acc[0][1], a0, w1);
        f32x2_fma(acc[0][2], a0, w2); f32x2_fma(acc[0][3], a0, w3);
        f32x2_fma(acc[1][0], a1, w0); f32x2_fma(acc[1][1], a1, w1);
        f32x2_fma(acc[1][2], a1, w2); f32x2_fma(acc[1][3], a1, w3);
        f32x2_fma(acc[2][0], a2, w0); f32x2_fma(acc[2][1], a2, w1);
        f32x2_fma(acc[2][2], a2, w2); f32x2_fma(acc[2][3], a2, w3);
        f32x2_fma(acc[3][0], a3, w0); f32x2_fma(acc[3][1], a3, w1);
        f32x2_fma(acc[3][2], a3, w2); f32x2_fma(acc[3][3], a3, w3);
    }

    float4 bv = reinterpret_cast<const float4*>(b)[tx];
#pragma unroll
    for (int p = 0; p < 4; p++) {
        int r0 = row0 + ty * 8 + 2 * p;
        float2 c0 = f32x2_unpack(acc[p][0]);
        float2 c1 = f32x2_unpack(acc[p][1]);
        float2 c2 = f32x2_unpack(acc[p][2]);
        float2 c3 = f32x2_unpack(acc[p][3]);
        float4 o0 = make_float4(c0.x + bv.x, c1.x + bv.y, c2.x + bv.z, c3.x + bv.w);
        float4 o1 = make_float4(c0.y + bv.x, c1.y + bv.y, c2.y + bv.z, c3.y + bv.w);
        if (GELU) {
            o0.x = gelu_exact(o0.x); o0.y = gelu_exact(o0.y);
            o0.z = gelu_exact(o0.z); o0.w = gelu_exact(o0.w);
            o1.x = gelu_exact(o1.x); o1.y = gelu_exact(o1.y);
            o1.z = gelu_exact(o1.z); o1.w = gelu_exact(o1.w);
        }
        if (r0 < n)
            *reinterpret_cast<float4*>(&C[(size_t)r0 * HIDDEN + tx * 4]) = o0;
        if (r0 + 1 < n)
            *reinterpret_cast<float4*>(&C[(size_t)(r0 + 1) * HIDDEN + tx * 4]) = o1;
    }
}

// ---------------- launch -----------------------------------------------------
extern "C" void kernel_launch(void* const* d_in, const int* in_sizes, int n_in,
                              void* d_out, int out_size) {
    const float* x = (const float*)d_in[0];
    const float* W = (const float*)d_in[1];
    const float* b = (const float*)d_in[2];
    const int* ei  = (const int*)d_in[3];

    const int n = in_sizes[0] / HIDDEN;   // 50000
    const int e = in_sizes[3] / 2;        // 800000
    const int* src = ei;
    const int* dst = ei + e;

    float* out = (float*)d_out;

    static float* p_h   = nullptr;
    static float* p_agg = nullptr;
    static int*   p_deg = nullptr;
    static int*   p_cur = nullptr;
    static cudaStream_t s2 = nullptr;
    static cudaEvent_t ev_fork = nullptr, ev_join = nullptr;
    if (!p_h) {
        cudaGetSymbolAddress((void**)&p_h, g_h);
        cudaGetSymbolAddress((void**)&p_agg, g_agg);
        cudaGetSymbolAddress((void**)&p_deg, g_degi);
        cudaGetSymbolAddress((void**)&p_cur, g_cur);
        cudaStreamCreateWithFlags(&s2, cudaStreamNonBlocking);
        cudaEventCreateWithFlags(&ev_fork, cudaEventDisableTiming);
        cudaEventCreateWithFlags(&ev_join, cudaEventDisableTiming);
    }

    const size_t smem_bytes = (HIDDEN * WT_STRIDE + HIDDEN * AT_STRIDE) * sizeof(float);
    cudaFuncSetAttribute(gemm_bias_kernel<false>,
                         cudaFuncAttributeMaxDynamicSharedMemorySize, (int)smem_bytes);
    cudaFuncSetAttribute(gemm_bias_kernel<true>,
                         cudaFuncAttributeMaxDynamicSharedMemorySize, (int)smem_bytes);

    const int gemm_blocks = (n + GEMM_ROWS - 1) / GEMM_ROWS;

    // ---- fork: GEMM1 (depends only on inputs) runs on side stream ----------
    cudaEventRecord(ev_fork, 0);
    cudaStreamWaitEvent(s2, ev_fork, 0);
    gemm_bias_kernel<false><<<gemm_blocks, 256, smem_bytes, s2>>>(x, W, b, p_h, n);
    cudaEventRecord(ev_join, s2);

    // ---- CSR build chain on main stream (concurrent with GEMM1) ------------
    cudaMemsetAsync(p_deg, 0, (size_t)n * sizeof(int));
    cudaMemsetAsync(p_cur, 0, (size_t)n * sizeof(int));
    deg_kernel<<<(e + 255) / 256, 256>>>(dst, e);
    int nscan = (n + 1023) / 1024;  // 49 <= 64
    scan_block_kernel<<<nscan, 1024>>>(n);       // also computes g_dinv
    scan_sums_kernel<<<1, 64>>>(nscan);
    scan_add_kernel<<<(n + 255) / 256, 256>>>(n);
    fill_kernel<<<(e + 255) / 256, 256>>>(src, dst, e);

    // ---- join: gather needs both h (GEMM1) and CSR ---------------------------
    cudaStreamWaitEvent(0, ev_join, 0);
    unsigned gthreads = (unsigned)n * 32u;
    gather_kernel<<<(gthreads + 255) / 256, 256>>>(n);

    // ---- out = gelu(agg @ W^T + b) -------------------------------------------
    gemm_bias_kernel<true><<<gemm_blocks, 256, smem_bytes>>>(p_agg, W, b, out, n);
}